// round 15
// baseline (speedup 1.0000x reference)
#include <cuda_runtime.h>

// MLP_89498528514757 — fused recommender MLP, fp32. Round 15:
// R13 (FFMA2, ncu 8.35us) with layer-2 weight loads vectorized to LDG.128:
// thread owns 4 consecutive j (warp = 128 consecutive j, coalesced),
// 16-way split-K -> 16 iters of LDG.128 + LDS.128 + 4 packs + 8 FFMA2.
// Post-prefetch LDG count 24 -> 12, serial k-loop 32 -> 16 iters.
// Layer 3/4 identical to R13.

#define NUM_USERS 100000
#define BATCH     1024
#define ROWS      4

typedef unsigned long long u64;

__device__ __forceinline__ u64 fma2(u64 a, u64 b, u64 c) {
    u64 d;
    asm("fma.rn.f32x2 %0, %1, %2, %3;" : "=l"(d) : "l"(a), "l"(b), "l"(c));
    return d;
}
__device__ __forceinline__ u64 pack2(float x) {
    u64 d;
    asm("mov.b64 %0, {%1, %1};" : "=l"(d) : "f"(x));
    return d;
}

__global__ __launch_bounds__(512, 2)
void mlp_fused_kernel(const int*   __restrict__ user_ids,
                      const int*   __restrict__ item_ids,
                      const float* __restrict__ W1, const float* __restrict__ b1,
                      const float* __restrict__ W2, const float* __restrict__ b2,
                      const float* __restrict__ W3, const float* __restrict__ b3,
                      const float* __restrict__ W4, const float* __restrict__ b4,
                      float*       __restrict__ out)
{
    __shared__ float4 h1t[256];                 // [k] -> rows 01|23   (4 KB)
    __shared__ union {
        float4 l2[16][128];                     // [ks][j] -> 4 rows  (32 KB)
        float4 l3[8][64];                       // [ks][j] -> 4 rows   (8 KB)
    } P;
    __shared__ float4 h2t[128];                 // [k] -> 4 rows       (2 KB)
    __shared__ float4 h3t[64];                  // [j] -> 4 rows       (1 KB)

    const int t    = threadIdx.x;               // 0..511
    const int row0 = blockIdx.x * ROWS;

    // ---------------- Layer 1: start the dependent DRAM chain FIRST --------
    const int k1 = t & 255;
    const int g  = t >> 8;                      // 0/1 -> rows {2g, 2g+1}
    const int ra = row0 + g * 2;
    const int ua = user_ids[ra],     ia = item_ids[ra];
    const int ub = user_ids[ra + 1], ib = item_ids[ra + 1];
    const float ga = W1[ua * 256 + k1], ea = W1[(NUM_USERS + ia) * 256 + k1];
    const float gb = W1[ub * 256 + k1], eb = W1[(NUM_USERS + ib) * 256 + k1];

    // ---- overlap while the gather is in flight ----------------------------
    // layer 2: jq = t&31 -> cols {4jq..4jq+3}; k-slice ks = t>>5 (0..15)
    const int jq = t & 31;
    const int ks = t >> 5;
    const float4* __restrict__ w2p =
        reinterpret_cast<const float4*>(W2) + (ks * 16) * 32 + jq;
    float4 w2pre[4];
    #pragma unroll
    for (int i = 0; i < 4; ++i) w2pre[i] = w2p[i * 32];   // head: 4 of 16 iters

    // layer 3: j3 = t&63, k-slice k83 = t>>6 (8-way, 16 iters, all in regs)
    const int j3  = t & 63;
    const int k83 = t >> 6;
    float w3pre[16];
    {
        const float* __restrict__ w3p = W3 + (k83 * 16) * 64 + j3;
        #pragma unroll
        for (int i = 0; i < 16; ++i) w3pre[i] = w3p[i * 64];
    }

    const float bj2 = b2[t >> 2];               // combine2: j = t>>2
    float w4a = 0.f, w4b = 0.f, bb4 = 0.f;
    if (t < 32) { w4a = W4[t]; w4b = W4[t + 32]; bb4 = b4[0]; }

    // finish layer 1: thread writes its 2 rows of h1t[k1] (8B STS)
    {
        const float bk = b1[k1];
        float2 h;
        h.x = fmaxf(ga + ea + bk, 0.f);
        h.y = fmaxf(gb + eb + bk, 0.f);
        *reinterpret_cast<float2*>(
            reinterpret_cast<float*>(&h1t[k1]) + g * 2) = h;
    }
    __syncthreads();

    // --- Layer 2: [4x256] @ W2[256x128], 16-way K, 4 j/thread, FFMA2 -------
    {
        u64 a0_01 = 0ull, a0_23 = 0ull;         // col 4jq+0
        u64 a1_01 = 0ull, a1_23 = 0ull;         // col 4jq+1
        u64 a2_01 = 0ull, a2_23 = 0ull;         // col 4jq+2
        u64 a3_01 = 0ull, a3_23 = 0ull;         // col 4jq+3
        #pragma unroll
        for (int kk = 0; kk < 4; ++kk) {        // weights already in regs
            const float4 w = w2pre[kk];
            const ulonglong2 v =
                *reinterpret_cast<const ulonglong2*>(&h1t[ks * 16 + kk]);
            const u64 w0 = pack2(w.x), w1 = pack2(w.y);
            const u64 w2r = pack2(w.z), w3r = pack2(w.w);
            a0_01 = fma2(v.x, w0, a0_01);  a0_23 = fma2(v.y, w0, a0_23);
            a1_01 = fma2(v.x, w1, a1_01);  a1_23 = fma2(v.y, w1, a1_23);
            a2_01 = fma2(v.x, w2r, a2_01); a2_23 = fma2(v.y, w2r, a2_23);
            a3_01 = fma2(v.x, w3r, a3_01); a3_23 = fma2(v.y, w3r, a3_23);
        }
        #pragma unroll
        for (int kk = 4; kk < 16; ++kk) {
            const float4 w = w2p[kk * 32];      // LDG.128, warp spans 512B
            const ulonglong2 v =
                *reinterpret_cast<const ulonglong2*>(&h1t[ks * 16 + kk]);
            const u64 w0 = pack2(w.x), w1 = pack2(w.y);
            const u64 w2r = pack2(w.z), w3r = pack2(w.w);
            a0_01 = fma2(v.x, w0, a0_01);  a0_23 = fma2(v.y, w0, a0_23);
            a1_01 = fma2(v.x, w1, a1_01);  a1_23 = fma2(v.y, w1, a1_23);
            a2_01 = fma2(v.x, w2r, a2_01); a2_23 = fma2(v.y, w2r, a2_23);
            a3_01 = fma2(v.x, w3r, a3_01); a3_23 = fma2(v.y, w3r, a3_23);
        }
        ulonglong2 s0; s0.x = a0_01; s0.y = a0_23;
        ulonglong2 s1; s1.x = a1_01; s1.y = a1_23;
        ulonglong2 s2; s2.x = a2_01; s2.y = a2_23;
        ulonglong2 s3; s3.x = a3_01; s3.y = a3_23;
        *reinterpret_cast<ulonglong2*>(&P.l2[ks][jq * 4 + 0]) = s0;
        *reinterpret_cast<ulonglong2*>(&P.l2[ks][jq * 4 + 1]) = s1;
        *reinterpret_cast<ulonglong2*>(&P.l2[ks][jq * 4 + 2]) = s2;
        *reinterpret_cast<ulonglong2*>(&P.l2[ks][jq * 4 + 3]) = s3;
    }
    __syncthreads();

    // combine layer-2 partials: all 512 threads, element (j = t>>2, r = t&3)
    {
        const int j = t >> 2, r = t & 3;
        float s = bj2;
        #pragma unroll
        for (int q = 0; q < 16; ++q)
            s += reinterpret_cast<const float*>(&P.l2[q][j])[r];
        reinterpret_cast<float*>(&h2t[j])[r] = fmaxf(s, 0.f);
    }
    __syncthreads();

    // ------- Layer 3: [4x128] @ W3[128x64], 8-way split-K, FFMA2 -----------
    {
        u64 a01 = 0ull, a23 = 0ull;
        #pragma unroll
        for (int kk = 0; kk < 16; ++kk) {
            const u64 ww = pack2(w3pre[kk]);
            const ulonglong2 v =
                *reinterpret_cast<const ulonglong2*>(&h2t[k83 * 16 + kk]);
            a01 = fma2(v.x, ww, a01);
            a23 = fma2(v.y, ww, a23);
        }
        ulonglong2 sv; sv.x = a01; sv.y = a23;
        *reinterpret_cast<ulonglong2*>(&P.l3[k83][j3]) = sv;
    }
    __syncthreads();

    // combine layer-3 partials: 256 threads, element (j = t>>2, r = t&3)
    if (t < 256) {
        const int j = t >> 2, r = t & 3;
        float s = b3[j];
        #pragma unroll
        for (int q = 0; q < 8; ++q)
            s += reinterpret_cast<const float*>(&P.l3[q][j])[r];
        reinterpret_cast<float*>(&h3t[j])[r] = fmaxf(s, 0.f);
    }
    __syncthreads();

    // ---------------- Layer 4: [4x64] @ W4[64x1] + b4 (warp 0) -------------
    if (t < 32) {
        const float4 va = h3t[t], vb = h3t[t + 32];
        float a0 = fmaf(va.x, w4a, vb.x * w4b);
        float a1 = fmaf(va.y, w4a, vb.y * w4b);
        float a2 = fmaf(va.z, w4a, vb.z * w4b);
        float a3 = fmaf(va.w, w4a, vb.w * w4b);
        #pragma unroll
        for (int off = 16; off > 0; off >>= 1) {
            a0 += __shfl_down_sync(0xffffffffu, a0, off);
            a1 += __shfl_down_sync(0xffffffffu, a1, off);
            a2 += __shfl_down_sync(0xffffffffu, a2, off);
            a3 += __shfl_down_sync(0xffffffffu, a3, off);
        }
        if (t == 0) {
            out[row0 + 0] = a0 + bb4;
            out[row0 + 1] = a1 + bb4;
            out[row0 + 2] = a2 + bb4;
            out[row0 + 3] = a3 + bb4;
        }
    }
}

extern "C" void kernel_launch(void* const* d_in, const int* in_sizes, int n_in,
                              void* d_out, int out_size)
{
    const int*   user_ids = (const int*)  d_in[0];
    const int*   item_ids = (const int*)  d_in[1];
    const float* W1       = (const float*)d_in[2];
    const float* b1       = (const float*)d_in[3];
    const float* W2       = (const float*)d_in[4];
    const float* b2       = (const float*)d_in[5];
    const float* W3       = (const float*)d_in[6];
    const float* b3       = (const float*)d_in[7];
    const float* W4       = (const float*)d_in[8];
    const float* b4       = (const float*)d_in[9];
    float*       out      = (float*)d_out;

    mlp_fused_kernel<<<BATCH / ROWS, 512>>>(user_ids, item_ids,
                                            W1, b1, W2, b2, W3, b3, W4, b4, out);
}

// round 16
// speedup vs baseline: 1.0030x; 1.0030x over previous
#include <cuda_runtime.h>

// MLP_89498528514757 — fused recommender MLP, fp32. Round 16:
// R13 champion (FFMA2, 8-way/8-way split-K, ncu 8.35us) with two
// critical-path cuts:
//  (1) int4-vectorized user/item id loads (one LDG.128 per table instead of
//      4 scalar LDGs at the head of the dependent gather chain);
//  (2) combine3 + layer 4 fused into warp 0 (reads the 8 layer-3 partials
//      directly: 16 conflict-free LDS.128, sum+ReLU+dot inline) — removes
//      one __syncthreads, the 256-thread combine phase, and h3t.

#define NUM_USERS 100000
#define BATCH     1024
#define ROWS      4

typedef unsigned long long u64;

__device__ __forceinline__ u64 fma2(u64 a, u64 b, u64 c) {
    u64 d;
    asm("fma.rn.f32x2 %0, %1, %2, %3;" : "=l"(d) : "l"(a), "l"(b), "l"(c));
    return d;
}
__device__ __forceinline__ u64 pack2(float x) {
    u64 d;
    asm("mov.b64 %0, {%1, %1};" : "=l"(d) : "f"(x));
    return d;
}

__global__ __launch_bounds__(512, 2)
void mlp_fused_kernel(const int*   __restrict__ user_ids,
                      const int*   __restrict__ item_ids,
                      const float* __restrict__ W1, const float* __restrict__ b1,
                      const float* __restrict__ W2, const float* __restrict__ b2,
                      const float* __restrict__ W3, const float* __restrict__ b3,
                      const float* __restrict__ W4, const float* __restrict__ b4,
                      float*       __restrict__ out)
{
    __shared__ float4 h1t[256];                 // [k] -> rows 01|23   (4 KB)
    __shared__ union {
        float4 l2[8][128];                      // [ks][j] -> 4 rows  (16 KB)
        float4 l3[8][64];                       // [ks][j] -> 4 rows   (8 KB)
    } P;
    __shared__ float4 h2t[128];                 // [k] -> 4 rows       (2 KB)

    const int t    = threadIdx.x;               // 0..511
    const int row0 = blockIdx.x * ROWS;

    // ---------------- Layer 1: dependent gather chain, vectorized head -----
    // One int4 load per id table (16B-aligned since row0 = 4*blockIdx).
    const int4 uid4 = *reinterpret_cast<const int4*>(user_ids + row0);
    const int4 iid4 = *reinterpret_cast<const int4*>(item_ids + row0);

    const int k1 = t & 255;
    const int g  = t >> 8;                      // 0/1 -> rows {2g, 2g+1}
    const int ua = (g == 0) ? uid4.x : uid4.z;
    const int ub = (g == 0) ? uid4.y : uid4.w;
    const int ia = (g == 0) ? iid4.x : iid4.z;
    const int ib = (g == 0) ? iid4.y : iid4.w;
    const float ga = W1[ua * 256 + k1], ea = W1[(NUM_USERS + ia) * 256 + k1];
    const float gb = W1[ub * 256 + k1], eb = W1[(NUM_USERS + ib) * 256 + k1];

    // ---- overlap while the gather is in flight ----------------------------
    // layer 2: j-pair jp = t&63 -> cols {2jp, 2jp+1}; k-slice ks = t>>6 (0..7)
    const int jp = t & 63;
    const int ks = t >> 6;
    const float2* __restrict__ w2p =
        reinterpret_cast<const float2*>(W2) + (ks * 32) * 64 + jp;
    float2 w2pre[8];
    #pragma unroll
    for (int i = 0; i < 8; ++i) w2pre[i] = w2p[i * 64];   // head: 8 of 32 iters

    // layer 3: j3 = t&63, k-slice k83 = t>>6 (8-way, 16 iters, all in regs)
    const int j3  = t & 63;
    const int k83 = t >> 6;
    float w3pre[16];
    {
        const float* __restrict__ w3p = W3 + (k83 * 16) * 64 + j3;
        #pragma unroll
        for (int i = 0; i < 16; ++i) w3pre[i] = w3p[i * 64];
    }

    const float bj2 = b2[t >> 2];               // combine2: j = t>>2
    float w4a = 0.f, w4b = 0.f, bb4 = 0.f, b3a = 0.f, b3b = 0.f;
    if (t < 32) {
        w4a = W4[t];      w4b = W4[t + 32];
        b3a = b3[t];      b3b = b3[t + 32];
        bb4 = b4[0];
    }

    // finish layer 1: thread writes its 2 rows of h1t[k1] (8B STS)
    {
        const float bk = b1[k1];
        float2 h;
        h.x = fmaxf(ga + ea + bk, 0.f);
        h.y = fmaxf(gb + eb + bk, 0.f);
        *reinterpret_cast<float2*>(
            reinterpret_cast<float*>(&h1t[k1]) + g * 2) = h;
    }
    __syncthreads();                            // BAR 1

    // ------- Layer 2: [4x256] @ W2[256x128], 8-way K, 2 j/thread, FFMA2 ----
    {
        u64 ae01 = 0ull, ae23 = 0ull;           // col 2jp:   rows 01 | 23
        u64 ao01 = 0ull, ao23 = 0ull;           // col 2jp+1: rows 01 | 23
        #pragma unroll
        for (int kk = 0; kk < 8; ++kk) {        // weights already in regs
            const float2 w = w2pre[kk];
            const ulonglong2 v =
                *reinterpret_cast<const ulonglong2*>(&h1t[ks * 32 + kk]);
            const u64 wx = pack2(w.x), wy = pack2(w.y);
            ae01 = fma2(v.x, wx, ae01);  ae23 = fma2(v.y, wx, ae23);
            ao01 = fma2(v.x, wy, ao01);  ao23 = fma2(v.y, wy, ao23);
        }
        #pragma unroll
        for (int kk = 8; kk < 32; ++kk) {
            const float2 w = w2p[kk * 64];      // LDG.64, warp spans 256B
            const ulonglong2 v =
                *reinterpret_cast<const ulonglong2*>(&h1t[ks * 32 + kk]);
            const u64 wx = pack2(w.x), wy = pack2(w.y);
            ae01 = fma2(v.x, wx, ae01);  ae23 = fma2(v.y, wx, ae23);
            ao01 = fma2(v.x, wy, ao01);  ao23 = fma2(v.y, wy, ao23);
        }
        ulonglong2 se; se.x = ae01; se.y = ae23;
        ulonglong2 so; so.x = ao01; so.y = ao23;
        *reinterpret_cast<ulonglong2*>(&P.l2[ks][jp * 2 + 0]) = se;  // STS.128
        *reinterpret_cast<ulonglong2*>(&P.l2[ks][jp * 2 + 1]) = so;
    }
    __syncthreads();                            // BAR 2

    // combine layer-2 partials: all 512 threads, element (j = t>>2, r = t&3)
    {
        const int j = t >> 2, r = t & 3;
        float s = bj2;
        #pragma unroll
        for (int q = 0; q < 8; ++q)
            s += reinterpret_cast<const float*>(&P.l2[q][j])[r];
        reinterpret_cast<float*>(&h2t[j])[r] = fmaxf(s, 0.f);
    }
    __syncthreads();                            // BAR 3

    // ------- Layer 3: [4x128] @ W3[128x64], 8-way split-K, FFMA2 -----------
    {
        u64 a01 = 0ull, a23 = 0ull;
        #pragma unroll
        for (int kk = 0; kk < 16; ++kk) {
            const u64 ww = pack2(w3pre[kk]);
            const ulonglong2 v =
                *reinterpret_cast<const ulonglong2*>(&h2t[k83 * 16 + kk]);
            a01 = fma2(v.x, ww, a01);
            a23 = fma2(v.y, ww, a23);
        }
        ulonglong2 sv; sv.x = a01; sv.y = a23;
        *reinterpret_cast<ulonglong2*>(&P.l3[k83][j3]) = sv;
    }
    __syncthreads();                            // BAR 4

    // ------- fused combine3 + Layer 4 (warp 0 only) ------------------------
    // out[row0+r] = b4 + sum_j W4[j] * relu(b3[j] + sum_q P.l3[q][j].row[r])
    if (t < 32) {
        float4 acc = make_float4(0.f, 0.f, 0.f, 0.f);
        #pragma unroll
        for (int jj = 0; jj < 2; ++jj) {
            const int   j  = t + jj * 32;
            const float bj = jj ? b3b : b3a;
            const float w4 = jj ? w4b : w4a;
            float4 s = make_float4(bj, bj, bj, bj);
            #pragma unroll
            for (int q = 0; q < 8; ++q) {       // LDS.128, conflict-free
                const float4 p = P.l3[q][j];
                s.x += p.x; s.y += p.y; s.z += p.z; s.w += p.w;
            }
            acc.x = fmaf(fmaxf(s.x, 0.f), w4, acc.x);
            acc.y = fmaf(fmaxf(s.y, 0.f), w4, acc.y);
            acc.z = fmaf(fmaxf(s.z, 0.f), w4, acc.z);
            acc.w = fmaf(fmaxf(s.w, 0.f), w4, acc.w);
        }
        #pragma unroll
        for (int off = 16; off > 0; off >>= 1) {
            acc.x += __shfl_down_sync(0xffffffffu, acc.x, off);
            acc.y += __shfl_down_sync(0xffffffffu, acc.y, off);
            acc.z += __shfl_down_sync(0xffffffffu, acc.z, off);
            acc.w += __shfl_down_sync(0xffffffffu, acc.w, off);
        }
        if (t == 0) {
            out[row0 + 0] = acc.x + bb4;
            out[row0 + 1] = acc.y + bb4;
            out[row0 + 2] = acc.z + bb4;
            out[row0 + 3] = acc.w + bb4;
        }
    }
}

extern "C" void kernel_launch(void* const* d_in, const int* in_sizes, int n_in,
                              void* d_out, int out_size)
{
    const int*   user_ids = (const int*)  d_in[0];
    const int*   item_ids = (const int*)  d_in[1];
    const float* W1       = (const float*)d_in[2];
    const float* b1       = (const float*)d_in[3];
    const float* W2       = (const float*)d_in[4];
    const float* b2       = (const float*)d_in[5];
    const float* W3       = (const float*)d_in[6];
    const float* b3       = (const float*)d_in[7];
    const float* W4       = (const float*)d_in[8];
    const float* b4       = (const float*)d_in[9];
    float*       out      = (float*)d_out;

    mlp_fused_kernel<<<BATCH / ROWS, 512>>>(user_ids, item_ids,
                                            W1, b1, W2, b2, W3, b3, W4, b4, out);
}